// round 1
// baseline (speedup 1.0000x reference)
#include <cuda_runtime.h>

#define MAXN 200000

// Scratch (device globals — no runtime allocation allowed)
__device__ float  g_deg[MAXN];
__device__ float  g_dinv[MAXN];
__device__ float4 g_hs1[MAXN * 4];   // layer-1 scaled features  h1raw*dinv  [N,16]
__device__ float4 g_t1 [MAXN * 4];   // layer-1 neighbor sums
__device__ float4 g_hs2[MAXN * 4];   // layer-2 scaled features
__device__ float4 g_t2 [MAXN * 4];   // layer-2 neighbor sums

// ---------------------------------------------------------------------------
// init: deg = 1 (self loop), t1 = t2 = 0
// ---------------------------------------------------------------------------
__global__ void k_init(int n) {
    int stride = gridDim.x * blockDim.x;
    int i0 = blockIdx.x * blockDim.x + threadIdx.x;
    float4 z = make_float4(0.f, 0.f, 0.f, 0.f);
    int total4 = n * 4;
    for (int i = i0; i < total4; i += stride) {
        g_t1[i] = z;
        g_t2[i] = z;
    }
    for (int i = i0; i < n; i += stride) g_deg[i] = 1.0f;
}

// ---------------------------------------------------------------------------
// degree: deg[dst] += 1 per edge
// ---------------------------------------------------------------------------
__global__ void k_deg(const int* __restrict__ dst, int E) {
    int e = blockIdx.x * blockDim.x + threadIdx.x;
    if (e < E) atomicAdd(&g_deg[dst[e]], 1.0f);
}

// ---------------------------------------------------------------------------
// GEMM1: hs1 = (x @ W1) * rsqrt(deg);  also stores dinv.
// Block: 256 threads, 64 nodes. x tile staged in smem (coalesced), padded
// stride 132 for bank-conflict-free reads. Each thread: 1 node, 4 outputs.
// ---------------------------------------------------------------------------
__global__ void k_gemm1(const float* __restrict__ x, const float* __restrict__ W1, int n) {
    __shared__ float xs[64 * 132];
    __shared__ float Ws[128 * 16];
    int t = threadIdx.x;
    int node0 = blockIdx.x * 64;

    for (int i = t; i < 128 * 16; i += 256) Ws[i] = W1[i];
    for (int i = t; i < 64 * 128; i += 256) {
        int node = i >> 7, k = i & 127;
        int gn = node0 + node;
        xs[node * 132 + k] = (gn < n) ? x[(size_t)gn * 128 + k] : 0.f;
    }
    __syncthreads();

    int node = t >> 2;          // 0..63
    int c4   = t & 3;           // output float4 index (channels c4*4..c4*4+3)
    int gn = node0 + node;
    if (gn >= n) return;

    const float4* xs4 = (const float4*)(xs + node * 132);
    const float4* Ws4 = (const float4*)Ws;
    float4 acc = make_float4(0.f, 0.f, 0.f, 0.f);
#pragma unroll
    for (int k4 = 0; k4 < 32; k4++) {
        float4 xv = xs4[k4];
        float4 w;
        w = Ws4[(4 * k4 + 0) * 4 + c4];
        acc.x += xv.x * w.x; acc.y += xv.x * w.y; acc.z += xv.x * w.z; acc.w += xv.x * w.w;
        w = Ws4[(4 * k4 + 1) * 4 + c4];
        acc.x += xv.y * w.x; acc.y += xv.y * w.y; acc.z += xv.y * w.z; acc.w += xv.y * w.w;
        w = Ws4[(4 * k4 + 2) * 4 + c4];
        acc.x += xv.z * w.x; acc.y += xv.z * w.y; acc.z += xv.z * w.z; acc.w += xv.z * w.w;
        w = Ws4[(4 * k4 + 3) * 4 + c4];
        acc.x += xv.w * w.x; acc.y += xv.w * w.y; acc.z += xv.w * w.z; acc.w += xv.w * w.w;
    }
    float di = rsqrtf(g_deg[gn]);
    if (c4 == 0) g_dinv[gn] = di;
    acc.x *= di; acc.y *= di; acc.z *= di; acc.w *= di;
    g_hs1[gn * 4 + c4] = acc;
}

// ---------------------------------------------------------------------------
// edge pass: t[dst] += hs[src]   (pure gather/scatter, 4 threads per edge)
// ---------------------------------------------------------------------------
__global__ void k_edge(const int* __restrict__ src, const int* __restrict__ dst,
                       int E4, int layer) {
    int gid = blockIdx.x * blockDim.x + threadIdx.x;
    if (gid >= E4) return;
    int e = gid >> 2;
    int p = gid & 3;
    int s = __ldg(src + e);
    int d = __ldg(dst + e);
    const float4* hs = layer ? g_hs2 : g_hs1;
    float4* tt = layer ? g_t2 : g_t1;
    float4 v = __ldg(hs + s * 4 + p);
    float* tp = (float*)(tt + d * 4 + p);
    asm volatile("red.global.add.v4.f32 [%0], {%1, %2, %3, %4};"
                 :: "l"(tp), "f"(v.x), "f"(v.y), "f"(v.z), "f"(v.w)
                 : "memory");
}

// ---------------------------------------------------------------------------
// combine: h1 = relu(dinv*(t1+hs1)+b1);  hs2 = (h1 @ W2) * dinv
// ---------------------------------------------------------------------------
__global__ void k_combine(const float* __restrict__ W2, const float* __restrict__ b1, int n) {
    __shared__ float W2s[256];
    __shared__ float b1s[16];
    int t = threadIdx.x;
    if (t < 256) W2s[t] = W2[t];
    if (t < 16)  b1s[t] = b1[t];
    __syncthreads();

    int i = blockIdx.x * blockDim.x + threadIdx.x;
    if (i >= n) return;
    float di = g_dinv[i];

    float h1[16];
#pragma unroll
    for (int q = 0; q < 4; q++) {
        float4 tv = g_t1[i * 4 + q];
        float4 hv = g_hs1[i * 4 + q];
        float v;
        v = di * (tv.x + hv.x) + b1s[q * 4 + 0]; h1[q * 4 + 0] = v > 0.f ? v : 0.f;
        v = di * (tv.y + hv.y) + b1s[q * 4 + 1]; h1[q * 4 + 1] = v > 0.f ? v : 0.f;
        v = di * (tv.z + hv.z) + b1s[q * 4 + 2]; h1[q * 4 + 2] = v > 0.f ? v : 0.f;
        v = di * (tv.w + hv.w) + b1s[q * 4 + 3]; h1[q * 4 + 3] = v > 0.f ? v : 0.f;
    }
#pragma unroll
    for (int q = 0; q < 4; q++) {
        float4 acc = make_float4(0.f, 0.f, 0.f, 0.f);
#pragma unroll
        for (int k = 0; k < 16; k++) {
            float hv = h1[k];
            acc.x += hv * W2s[k * 16 + q * 4 + 0];
            acc.y += hv * W2s[k * 16 + q * 4 + 1];
            acc.z += hv * W2s[k * 16 + q * 4 + 2];
            acc.w += hv * W2s[k * 16 + q * 4 + 3];
        }
        acc.x *= di; acc.y *= di; acc.z *= di; acc.w *= di;
        g_hs2[i * 4 + q] = acc;
    }
}

// ---------------------------------------------------------------------------
// final: h2 = relu(dinv*(t2+hs2)+b2); GRU (h0=0 => gh=b_hh); out = h' @ Wfc.T + bfc
// ---------------------------------------------------------------------------
__device__ __forceinline__ float sigmoidf_(float x) { return 1.0f / (1.0f + expf(-x)); }

__global__ void k_final(const float* __restrict__ b2,
                        const float* __restrict__ w_ih, const float* __restrict__ b_ih,
                        const float* __restrict__ b_hh,
                        const float* __restrict__ Wfc, const float* __restrict__ bfc,
                        float* __restrict__ out, int n) {
    __shared__ float wih_s[48 * 16];
    __shared__ float bih_s[48];
    __shared__ float bhh_s[48];
    __shared__ float wfc_s[32 * 16];
    __shared__ float bfc_s[32];
    __shared__ float b2s[16];
    int t = threadIdx.x;
    for (int i = t; i < 48 * 16; i += blockDim.x) wih_s[i] = w_ih[i];
    for (int i = t; i < 32 * 16; i += blockDim.x) wfc_s[i] = Wfc[i];
    if (t < 48) { bih_s[t] = b_ih[t]; bhh_s[t] = b_hh[t]; }
    if (t < 32) bfc_s[t] = bfc[t];
    if (t < 16) b2s[t] = b2[t];
    __syncthreads();

    int i = blockIdx.x * blockDim.x + threadIdx.x;
    if (i >= n) return;
    float di = g_dinv[i];

    float h2[16];
#pragma unroll
    for (int q = 0; q < 4; q++) {
        float4 tv = g_t2[i * 4 + q];
        float4 hv = g_hs2[i * 4 + q];
        float v;
        v = di * (tv.x + hv.x) + b2s[q * 4 + 0]; h2[q * 4 + 0] = v > 0.f ? v : 0.f;
        v = di * (tv.y + hv.y) + b2s[q * 4 + 1]; h2[q * 4 + 1] = v > 0.f ? v : 0.f;
        v = di * (tv.z + hv.z) + b2s[q * 4 + 2]; h2[q * 4 + 2] = v > 0.f ? v : 0.f;
        v = di * (tv.w + hv.w) + b2s[q * 4 + 3]; h2[q * 4 + 3] = v > 0.f ? v : 0.f;
    }

    float hout[16];
#pragma unroll
    for (int k = 0; k < 16; k++) {
        float ar = bih_s[k], az = bih_s[16 + k], an = bih_s[32 + k];
#pragma unroll
        for (int c = 0; c < 16; c++) {
            float hv = h2[c];
            ar += hv * wih_s[k * 16 + c];
            az += hv * wih_s[(16 + k) * 16 + c];
            an += hv * wih_s[(32 + k) * 16 + c];
        }
        float r = sigmoidf_(ar + bhh_s[k]);
        float z = sigmoidf_(az + bhh_s[16 + k]);
        float nn = tanhf(an + r * bhh_s[32 + k]);
        hout[k] = (1.0f - z) * nn;
    }

    float4* outp = (float4*)(out + (size_t)i * 32);
#pragma unroll
    for (int q = 0; q < 8; q++) {
        float4 o;
        float a0 = bfc_s[q * 4 + 0], a1 = bfc_s[q * 4 + 1];
        float a2 = bfc_s[q * 4 + 2], a3 = bfc_s[q * 4 + 3];
#pragma unroll
        for (int k = 0; k < 16; k++) {
            float hv = hout[k];
            a0 += hv * wfc_s[(q * 4 + 0) * 16 + k];
            a1 += hv * wfc_s[(q * 4 + 1) * 16 + k];
            a2 += hv * wfc_s[(q * 4 + 2) * 16 + k];
            a3 += hv * wfc_s[(q * 4 + 3) * 16 + k];
        }
        o.x = a0; o.y = a1; o.z = a2; o.w = a3;
        outp[q] = o;
    }
}

// ---------------------------------------------------------------------------
extern "C" void kernel_launch(void* const* d_in, const int* in_sizes, int n_in,
                              void* d_out, int out_size) {
    const float* x    = (const float*)d_in[0];
    const int*   ei   = (const int*)  d_in[1];
    // d_in[2] = batch (only used for N)
    const float* W1   = (const float*)d_in[3];
    const float* b1   = (const float*)d_in[4];
    const float* W2   = (const float*)d_in[5];
    const float* b2   = (const float*)d_in[6];
    const float* w_ih = (const float*)d_in[7];
    // d_in[8] = w_hh (unused: h0 = 0)
    const float* b_ih = (const float*)d_in[9];
    const float* b_hh = (const float*)d_in[10];
    const float* Wfc  = (const float*)d_in[11];
    const float* bfc  = (const float*)d_in[12];
    float* out = (float*)d_out;

    int n = in_sizes[2];           // N nodes (batch array length)
    int E = in_sizes[1] / 2;       // edges
    const int* src = ei;
    const int* dst = ei + E;

    k_init<<<1024, 256>>>(n);
    k_deg<<<(E + 255) / 256, 256>>>(dst, E);
    k_gemm1<<<(n + 63) / 64, 256>>>(x, W1, n);

    int E4 = E * 4;
    k_edge<<<(E4 + 255) / 256, 256>>>(src, dst, E4, 0);
    k_combine<<<(n + 255) / 256, 256>>>(W2, b1, n);
    k_edge<<<(E4 + 255) / 256, 256>>>(src, dst, E4, 1);
    k_final<<<(n + 127) / 128, 128>>>(b2, w_ih, b_ih, b_hh, Wfc, bfc, out, n);
}

// round 2
// speedup vs baseline: 1.0058x; 1.0058x over previous
#include <cuda_runtime.h>
#include <cuda_fp16.h>

#define MAXN 200000

// Scratch (device globals — no runtime allocation allowed)
__device__ float   g_deg[MAXN];
__device__ float   g_dinv[MAXN];
__device__ __half2 g_hs1h[MAXN * 8];  // layer-1 scaled features (fp16)  [N,16]
__device__ __half2 g_hs2h[MAXN * 8];  // layer-2 scaled features (fp16)
__device__ float4  g_t1[MAXN * 4];    // layer-1 neighbor sums (fp32 accum)
__device__ float4  g_t2[MAXN * 4];    // layer-2 neighbor sums

// ---------------------------------------------------------------------------
// init: deg = 1 (self loop). t1/t2 zeroing is folded into gemm1/combine.
// ---------------------------------------------------------------------------
__global__ void k_init(int n) {
    int i = blockIdx.x * blockDim.x + threadIdx.x;
    if (i < n) g_deg[i] = 1.0f;
}

// ---------------------------------------------------------------------------
// degree: deg[dst] += 1 per edge
// ---------------------------------------------------------------------------
__global__ void k_deg(const int* __restrict__ dst, int E) {
    int e = blockIdx.x * blockDim.x + threadIdx.x;
    if (e < E) atomicAdd(&g_deg[dst[e]], 1.0f);
}

// ---------------------------------------------------------------------------
// GEMM1: hs1 = (x @ W1) * rsqrt(deg) -> fp16; also stores dinv and zeros t1.
// Block: 256 threads, 64 nodes. x tile staged in smem, padded stride 132.
// ---------------------------------------------------------------------------
__global__ void k_gemm1(const float* __restrict__ x, const float* __restrict__ W1, int n) {
    __shared__ float xs[64 * 132];
    __shared__ float Ws[128 * 16];
    int t = threadIdx.x;
    int node0 = blockIdx.x * 64;

    for (int i = t; i < 128 * 16; i += 256) Ws[i] = W1[i];
    for (int i = t; i < 64 * 128; i += 256) {
        int node = i >> 7, k = i & 127;
        int gn = node0 + node;
        xs[node * 132 + k] = (gn < n) ? x[(size_t)gn * 128 + k] : 0.f;
    }
    __syncthreads();

    int node = t >> 2;          // 0..63
    int c4   = t & 3;           // output float4 index
    int gn = node0 + node;
    if (gn >= n) return;

    const float4* xs4 = (const float4*)(xs + node * 132);
    const float4* Ws4 = (const float4*)Ws;
    float4 acc = make_float4(0.f, 0.f, 0.f, 0.f);
#pragma unroll
    for (int k4 = 0; k4 < 32; k4++) {
        float4 xv = xs4[k4];
        float4 w;
        w = Ws4[(4 * k4 + 0) * 4 + c4];
        acc.x += xv.x * w.x; acc.y += xv.x * w.y; acc.z += xv.x * w.z; acc.w += xv.x * w.w;
        w = Ws4[(4 * k4 + 1) * 4 + c4];
        acc.x += xv.y * w.x; acc.y += xv.y * w.y; acc.z += xv.y * w.z; acc.w += xv.y * w.w;
        w = Ws4[(4 * k4 + 2) * 4 + c4];
        acc.x += xv.z * w.x; acc.y += xv.z * w.y; acc.z += xv.z * w.z; acc.w += xv.z * w.w;
        w = Ws4[(4 * k4 + 3) * 4 + c4];
        acc.x += xv.w * w.x; acc.y += xv.w * w.y; acc.z += xv.w * w.z; acc.w += xv.w * w.w;
    }
    float di = rsqrtf(g_deg[gn]);
    if (c4 == 0) g_dinv[gn] = di;
    acc.x *= di; acc.y *= di; acc.z *= di; acc.w *= di;

    __half2 h0 = __float22half2_rn(make_float2(acc.x, acc.y));
    __half2 h1 = __float22half2_rn(make_float2(acc.z, acc.w));
    g_hs1h[gn * 8 + c4 * 2 + 0] = h0;
    g_hs1h[gn * 8 + c4 * 2 + 1] = h1;
    g_t1[gn * 4 + c4] = make_float4(0.f, 0.f, 0.f, 0.f);
}

// ---------------------------------------------------------------------------
// edge pass: t[dst] += hs[src]  (fp16 gather, fp32 red). 4 threads / edge.
// ---------------------------------------------------------------------------
__global__ void k_edge(const int* __restrict__ src, const int* __restrict__ dst,
                       int E4, int layer) {
    int gid = blockIdx.x * blockDim.x + threadIdx.x;
    if (gid >= E4) return;
    int e = gid >> 2;
    int p = gid & 3;
    int s = __ldg(src + e);
    int d = __ldg(dst + e);
    const __half2* hs = layer ? g_hs2h : g_hs1h;
    float4* tt = layer ? g_t2 : g_t1;

    uint2 raw = __ldg((const uint2*)(hs + s * 8 + p * 2));
    __half2 a = *(const __half2*)&raw.x;
    __half2 b = *(const __half2*)&raw.y;
    float2 f0 = __half22float2(a);
    float2 f1 = __half22float2(b);

    float* tp = (float*)(tt + d * 4 + p);
    asm volatile("red.global.add.v4.f32 [%0], {%1, %2, %3, %4};"
                 :: "l"(tp), "f"(f0.x), "f"(f0.y), "f"(f1.x), "f"(f1.y)
                 : "memory");
}

// ---------------------------------------------------------------------------
// combine: h1 = relu(dinv*(t1+hs1)+b1); hs2 = (h1 @ W2)*dinv -> fp16; zero t2.
// ---------------------------------------------------------------------------
__global__ void k_combine(const float* __restrict__ W2, const float* __restrict__ b1, int n) {
    __shared__ float W2s[256];
    __shared__ float b1s[16];
    int t = threadIdx.x;
    if (t < 256) W2s[t] = W2[t];
    if (t < 16)  b1s[t] = b1[t];
    __syncthreads();

    int i = blockIdx.x * blockDim.x + threadIdx.x;
    if (i >= n) return;
    float di = g_dinv[i];

    float h1[16];
#pragma unroll
    for (int q = 0; q < 4; q++) {
        float4 tv = g_t1[i * 4 + q];
        float2 s0 = __half22float2(g_hs1h[i * 8 + q * 2 + 0]);
        float2 s1 = __half22float2(g_hs1h[i * 8 + q * 2 + 1]);
        float v;
        v = di * (tv.x + s0.x) + b1s[q * 4 + 0]; h1[q * 4 + 0] = v > 0.f ? v : 0.f;
        v = di * (tv.y + s0.y) + b1s[q * 4 + 1]; h1[q * 4 + 1] = v > 0.f ? v : 0.f;
        v = di * (tv.z + s1.x) + b1s[q * 4 + 2]; h1[q * 4 + 2] = v > 0.f ? v : 0.f;
        v = di * (tv.w + s1.y) + b1s[q * 4 + 3]; h1[q * 4 + 3] = v > 0.f ? v : 0.f;
    }
#pragma unroll
    for (int q = 0; q < 4; q++) {
        float a0 = 0.f, a1 = 0.f, a2 = 0.f, a3 = 0.f;
#pragma unroll
        for (int k = 0; k < 16; k++) {
            float hv = h1[k];
            a0 += hv * W2s[k * 16 + q * 4 + 0];
            a1 += hv * W2s[k * 16 + q * 4 + 1];
            a2 += hv * W2s[k * 16 + q * 4 + 2];
            a3 += hv * W2s[k * 16 + q * 4 + 3];
        }
        __half2 h0 = __float22half2_rn(make_float2(a0 * di, a1 * di));
        __half2 h1p = __float22half2_rn(make_float2(a2 * di, a3 * di));
        g_hs2h[i * 8 + q * 2 + 0] = h0;
        g_hs2h[i * 8 + q * 2 + 1] = h1p;
        g_t2[i * 4 + q] = make_float4(0.f, 0.f, 0.f, 0.f);
    }
}

// ---------------------------------------------------------------------------
// final: h2 = relu(dinv*(t2+hs2)+b2); GRU (h0=0 => gh=b_hh); out = h' @ Wfc.T + bfc
// ---------------------------------------------------------------------------
__device__ __forceinline__ float sigmoidf_(float x) { return 1.0f / (1.0f + expf(-x)); }

__global__ void k_final(const float* __restrict__ b2,
                        const float* __restrict__ w_ih, const float* __restrict__ b_ih,
                        const float* __restrict__ b_hh,
                        const float* __restrict__ Wfc, const float* __restrict__ bfc,
                        float* __restrict__ out, int n) {
    __shared__ float wih_s[48 * 16];
    __shared__ float bih_s[48];
    __shared__ float bhh_s[48];
    __shared__ float wfc_s[32 * 16];
    __shared__ float bfc_s[32];
    __shared__ float b2s[16];
    int t = threadIdx.x;
    for (int i = t; i < 48 * 16; i += blockDim.x) wih_s[i] = w_ih[i];
    for (int i = t; i < 32 * 16; i += blockDim.x) wfc_s[i] = Wfc[i];
    if (t < 48) { bih_s[t] = b_ih[t]; bhh_s[t] = b_hh[t]; }
    if (t < 32) bfc_s[t] = bfc[t];
    if (t < 16) b2s[t] = b2[t];
    __syncthreads();

    int i = blockIdx.x * blockDim.x + threadIdx.x;
    if (i >= n) return;
    float di = g_dinv[i];

    float h2[16];
#pragma unroll
    for (int q = 0; q < 4; q++) {
        float4 tv = g_t2[i * 4 + q];
        float2 s0 = __half22float2(g_hs2h[i * 8 + q * 2 + 0]);
        float2 s1 = __half22float2(g_hs2h[i * 8 + q * 2 + 1]);
        float v;
        v = di * (tv.x + s0.x) + b2s[q * 4 + 0]; h2[q * 4 + 0] = v > 0.f ? v : 0.f;
        v = di * (tv.y + s0.y) + b2s[q * 4 + 1]; h2[q * 4 + 1] = v > 0.f ? v : 0.f;
        v = di * (tv.z + s1.x) + b2s[q * 4 + 2]; h2[q * 4 + 2] = v > 0.f ? v : 0.f;
        v = di * (tv.w + s1.y) + b2s[q * 4 + 3]; h2[q * 4 + 3] = v > 0.f ? v : 0.f;
    }

    float hout[16];
#pragma unroll
    for (int k = 0; k < 16; k++) {
        float ar = bih_s[k], az = bih_s[16 + k], an = bih_s[32 + k];
#pragma unroll
        for (int c = 0; c < 16; c++) {
            float hv = h2[c];
            ar += hv * wih_s[k * 16 + c];
            az += hv * wih_s[(16 + k) * 16 + c];
            an += hv * wih_s[(32 + k) * 16 + c];
        }
        float r = sigmoidf_(ar + bhh_s[k]);
        float z = sigmoidf_(az + bhh_s[16 + k]);
        float nn = tanhf(an + r * bhh_s[32 + k]);
        hout[k] = (1.0f - z) * nn;
    }

    float4* outp = (float4*)(out + (size_t)i * 32);
#pragma unroll
    for (int q = 0; q < 8; q++) {
        float4 o;
        float a0 = bfc_s[q * 4 + 0], a1 = bfc_s[q * 4 + 1];
        float a2 = bfc_s[q * 4 + 2], a3 = bfc_s[q * 4 + 3];
#pragma unroll
        for (int k = 0; k < 16; k++) {
            float hv = hout[k];
            a0 += hv * wfc_s[(q * 4 + 0) * 16 + k];
            a1 += hv * wfc_s[(q * 4 + 1) * 16 + k];
            a2 += hv * wfc_s[(q * 4 + 2) * 16 + k];
            a3 += hv * wfc_s[(q * 4 + 3) * 16 + k];
        }
        o.x = a0; o.y = a1; o.z = a2; o.w = a3;
        outp[q] = o;
    }
}

// ---------------------------------------------------------------------------
extern "C" void kernel_launch(void* const* d_in, const int* in_sizes, int n_in,
                              void* d_out, int out_size) {
    const float* x    = (const float*)d_in[0];
    const int*   ei   = (const int*)  d_in[1];
    const float* W1   = (const float*)d_in[3];
    const float* b1   = (const float*)d_in[4];
    const float* W2   = (const float*)d_in[5];
    const float* b2   = (const float*)d_in[6];
    const float* w_ih = (const float*)d_in[7];
    const float* b_ih = (const float*)d_in[9];
    const float* b_hh = (const float*)d_in[10];
    const float* Wfc  = (const float*)d_in[11];
    const float* bfc  = (const float*)d_in[12];
    float* out = (float*)d_out;

    int n = in_sizes[2];           // N nodes
    int E = in_sizes[1] / 2;       // edges
    const int* src = ei;
    const int* dst = ei + E;

    k_init<<<(n + 255) / 256, 256>>>(n);
    k_deg<<<(E + 255) / 256, 256>>>(dst, E);
    k_gemm1<<<(n + 63) / 64, 256>>>(x, W1, n);

    int E4 = E * 4;
    k_edge<<<(E4 + 255) / 256, 256>>>(src, dst, E4, 0);
    k_combine<<<(n + 255) / 256, 256>>>(W2, b1, n);
    k_edge<<<(E4 + 255) / 256, 256>>>(src, dst, E4, 1);
    k_final<<<(n + 127) / 128, 128>>>(b2, w_ih, b_ih, b_hh, Wfc, bfc, out, n);
}

// round 3
// speedup vs baseline: 1.1568x; 1.1502x over previous
#include <cuda_runtime.h>
#include <cuda_fp16.h>

#define MAXN 200000
#define MAXE 6500000

// Scratch (device globals — no runtime allocation allowed)
__device__ int     g_cnt[MAXN];       // in-degree (without self loop)
__device__ int     g_rowptr[MAXN];    // CSR row start (exclusive scan of cnt)
__device__ int     g_cursor[MAXN];    // fill cursors
__device__ int     g_bsums[256];      // block sums for scan
__device__ int     g_csr[MAXE];       // src indices grouped by dst
__device__ float   g_dinv[MAXN];
__device__ __half2 g_hs1h[MAXN * 8];  // layer-1 scaled features (fp16) [N,16]
__device__ __half2 g_hs2h[MAXN * 8];  // layer-2 scaled features (fp16)
__device__ float4  g_t1[MAXN * 4];    // layer-1 neighbor sums (fp32)
__device__ float4  g_t2[MAXN * 4];    // layer-2 neighbor sums

// ---------------------------------------------------------------------------
__global__ void k_zero_cnt(int n) {
    int i = blockIdx.x * blockDim.x + threadIdx.x;
    if (i < n) g_cnt[i] = 0;
}

__global__ void k_count(const int* __restrict__ dst, int E) {
    int e = blockIdx.x * blockDim.x + threadIdx.x;
    if (e < E) atomicAdd(&g_cnt[dst[e]], 1);
}

// ---------------------------------------------------------------------------
// 3-kernel exclusive scan of g_cnt -> g_rowptr (and g_cursor copy).
// 1024 elements per block, <=256 blocks.
// ---------------------------------------------------------------------------
__global__ void k_scan1(int n) {
    __shared__ int sh[256];
    int b = blockIdx.x, t = threadIdx.x;
    int i0 = b * 1024 + t * 4;
    int s = 0;
#pragma unroll
    for (int k = 0; k < 4; k++) { int i = i0 + k; if (i < n) s += g_cnt[i]; }
    sh[t] = s; __syncthreads();
    for (int off = 128; off > 0; off >>= 1) {
        if (t < off) sh[t] += sh[t + off];
        __syncthreads();
    }
    if (t == 0) g_bsums[b] = sh[0];
}

__global__ void k_scan2(int nb) {
    __shared__ int sh[256];
    int t = threadIdx.x;
    int v = (t < nb) ? g_bsums[t] : 0;
    sh[t] = v; __syncthreads();
    for (int off = 1; off < 256; off <<= 1) {
        int a = (t >= off) ? sh[t - off] : 0;
        __syncthreads();
        sh[t] += a;
        __syncthreads();
    }
    if (t < nb) g_bsums[t] = sh[t] - v;   // exclusive
}

__global__ void k_scan3(int n) {
    __shared__ int sh[256];
    int b = blockIdx.x, t = threadIdx.x;
    int i0 = b * 1024 + t * 4;
    int c[4]; int s = 0;
#pragma unroll
    for (int k = 0; k < 4; k++) { int i = i0 + k; c[k] = (i < n) ? g_cnt[i] : 0; s += c[k]; }
    int tot = s;
    sh[t] = tot; __syncthreads();
    for (int off = 1; off < 256; off <<= 1) {
        int a = (t >= off) ? sh[t - off] : 0;
        __syncthreads();
        sh[t] += a;
        __syncthreads();
    }
    int run = sh[t] - tot + g_bsums[b];
#pragma unroll
    for (int k = 0; k < 4; k++) {
        int i = i0 + k;
        if (i < n) { g_rowptr[i] = run; g_cursor[i] = run; run += c[k]; }
    }
}

__global__ void k_fill(const int* __restrict__ src, const int* __restrict__ dst, int E) {
    int e = blockIdx.x * blockDim.x + threadIdx.x;
    if (e >= E) return;
    int d = dst[e];
    int pos = atomicAdd(&g_cursor[d], 1);
    g_csr[pos] = src[e];
}

// ---------------------------------------------------------------------------
// GEMM1: hs1 = (x @ W1) * rsqrt(deg) -> fp16; also stores dinv.
// ---------------------------------------------------------------------------
__global__ void k_gemm1(const float* __restrict__ x, const float* __restrict__ W1, int n) {
    __shared__ float xs[64 * 132];
    __shared__ float Ws[128 * 16];
    int t = threadIdx.x;
    int node0 = blockIdx.x * 64;

    for (int i = t; i < 128 * 16; i += 256) Ws[i] = W1[i];
    for (int i = t; i < 64 * 128; i += 256) {
        int node = i >> 7, k = i & 127;
        int gn = node0 + node;
        xs[node * 132 + k] = (gn < n) ? x[(size_t)gn * 128 + k] : 0.f;
    }
    __syncthreads();

    int node = t >> 2;
    int c4   = t & 3;
    int gn = node0 + node;
    if (gn >= n) return;

    const float4* xs4 = (const float4*)(xs + node * 132);
    const float4* Ws4 = (const float4*)Ws;
    float4 acc = make_float4(0.f, 0.f, 0.f, 0.f);
#pragma unroll
    for (int k4 = 0; k4 < 32; k4++) {
        float4 xv = xs4[k4];
        float4 w;
        w = Ws4[(4 * k4 + 0) * 4 + c4];
        acc.x += xv.x * w.x; acc.y += xv.x * w.y; acc.z += xv.x * w.z; acc.w += xv.x * w.w;
        w = Ws4[(4 * k4 + 1) * 4 + c4];
        acc.x += xv.y * w.x; acc.y += xv.y * w.y; acc.z += xv.y * w.z; acc.w += xv.y * w.w;
        w = Ws4[(4 * k4 + 2) * 4 + c4];
        acc.x += xv.z * w.x; acc.y += xv.z * w.y; acc.z += xv.z * w.z; acc.w += xv.z * w.w;
        w = Ws4[(4 * k4 + 3) * 4 + c4];
        acc.x += xv.w * w.x; acc.y += xv.w * w.y; acc.z += xv.w * w.z; acc.w += xv.w * w.w;
    }
    float di = rsqrtf((float)g_cnt[gn] + 1.0f);
    if (c4 == 0) g_dinv[gn] = di;
    acc.x *= di; acc.y *= di; acc.z *= di; acc.w *= di;

    g_hs1h[gn * 8 + c4 * 2 + 0] = __float22half2_rn(make_float2(acc.x, acc.y));
    g_hs1h[gn * 8 + c4 * 2 + 1] = __float22half2_rn(make_float2(acc.z, acc.w));
}

// ---------------------------------------------------------------------------
// gather pass: t[i] = sum_{j in adj(i)} hs[src_j].  8 threads per node,
// each thread owns one half2 (2 channels). No atomics.
// ---------------------------------------------------------------------------
__global__ void k_gather(int n, int layer) {
    int gid = blockIdx.x * blockDim.x + threadIdx.x;
    int node = gid >> 3;
    int sub  = gid & 7;
    if (node >= n) return;
    const unsigned* hs = (const unsigned*)(layer ? g_hs2h : g_hs1h);
    float2* tt = (float2*)(layer ? g_t2 : g_t1);

    int row = g_rowptr[node];
    int cnt = g_cnt[node];
    const int* cs = g_csr + row;

    float ax = 0.f, ay = 0.f;
    int j = 0;
    for (; j + 4 <= cnt; j += 4) {
        int s0 = __ldg(cs + j + 0);
        int s1 = __ldg(cs + j + 1);
        int s2 = __ldg(cs + j + 2);
        int s3 = __ldg(cs + j + 3);
        unsigned u0 = __ldg(hs + s0 * 8 + sub);
        unsigned u1 = __ldg(hs + s1 * 8 + sub);
        unsigned u2 = __ldg(hs + s2 * 8 + sub);
        unsigned u3 = __ldg(hs + s3 * 8 + sub);
        float2 f;
        f = __half22float2(*(const __half2*)&u0); ax += f.x; ay += f.y;
        f = __half22float2(*(const __half2*)&u1); ax += f.x; ay += f.y;
        f = __half22float2(*(const __half2*)&u2); ax += f.x; ay += f.y;
        f = __half22float2(*(const __half2*)&u3); ax += f.x; ay += f.y;
    }
    for (; j < cnt; j++) {
        int s = __ldg(cs + j);
        unsigned u = __ldg(hs + s * 8 + sub);
        float2 f = __half22float2(*(const __half2*)&u);
        ax += f.x; ay += f.y;
    }
    tt[node * 8 + sub] = make_float2(ax, ay);
}

// ---------------------------------------------------------------------------
// combine: h1 = relu(dinv*(t1+hs1)+b1); hs2 = (h1 @ W2)*dinv -> fp16.
// ---------------------------------------------------------------------------
__global__ void k_combine(const float* __restrict__ W2, const float* __restrict__ b1, int n) {
    __shared__ float W2s[256];
    __shared__ float b1s[16];
    int t = threadIdx.x;
    if (t < 256) W2s[t] = W2[t];
    if (t < 16)  b1s[t] = b1[t];
    __syncthreads();

    int i = blockIdx.x * blockDim.x + threadIdx.x;
    if (i >= n) return;
    float di = g_dinv[i];

    float h1[16];
#pragma unroll
    for (int q = 0; q < 4; q++) {
        float4 tv = g_t1[i * 4 + q];
        float2 s0 = __half22float2(g_hs1h[i * 8 + q * 2 + 0]);
        float2 s1 = __half22float2(g_hs1h[i * 8 + q * 2 + 1]);
        float v;
        v = di * (tv.x + s0.x) + b1s[q * 4 + 0]; h1[q * 4 + 0] = v > 0.f ? v : 0.f;
        v = di * (tv.y + s0.y) + b1s[q * 4 + 1]; h1[q * 4 + 1] = v > 0.f ? v : 0.f;
        v = di * (tv.z + s1.x) + b1s[q * 4 + 2]; h1[q * 4 + 2] = v > 0.f ? v : 0.f;
        v = di * (tv.w + s1.y) + b1s[q * 4 + 3]; h1[q * 4 + 3] = v > 0.f ? v : 0.f;
    }
#pragma unroll
    for (int q = 0; q < 4; q++) {
        float a0 = 0.f, a1 = 0.f, a2 = 0.f, a3 = 0.f;
#pragma unroll
        for (int k = 0; k < 16; k++) {
            float hv = h1[k];
            a0 += hv * W2s[k * 16 + q * 4 + 0];
            a1 += hv * W2s[k * 16 + q * 4 + 1];
            a2 += hv * W2s[k * 16 + q * 4 + 2];
            a3 += hv * W2s[k * 16 + q * 4 + 3];
        }
        g_hs2h[i * 8 + q * 2 + 0] = __float22half2_rn(make_float2(a0 * di, a1 * di));
        g_hs2h[i * 8 + q * 2 + 1] = __float22half2_rn(make_float2(a2 * di, a3 * di));
    }
}

// ---------------------------------------------------------------------------
// final: h2 = relu(dinv*(t2+hs2)+b2); GRU (h0=0 => gh=b_hh); out = h' @ Wfc.T + bfc
// ---------------------------------------------------------------------------
__device__ __forceinline__ float sigmoidf_(float x) { return 1.0f / (1.0f + expf(-x)); }

__global__ void k_final(const float* __restrict__ b2,
                        const float* __restrict__ w_ih, const float* __restrict__ b_ih,
                        const float* __restrict__ b_hh,
                        const float* __restrict__ Wfc, const float* __restrict__ bfc,
                        float* __restrict__ out, int n) {
    __shared__ float wih_s[48 * 16];
    __shared__ float bih_s[48];
    __shared__ float bhh_s[48];
    __shared__ float wfc_s[32 * 16];
    __shared__ float bfc_s[32];
    __shared__ float b2s[16];
    int t = threadIdx.x;
    for (int i = t; i < 48 * 16; i += blockDim.x) wih_s[i] = w_ih[i];
    for (int i = t; i < 32 * 16; i += blockDim.x) wfc_s[i] = Wfc[i];
    if (t < 48) { bih_s[t] = b_ih[t]; bhh_s[t] = b_hh[t]; }
    if (t < 32) bfc_s[t] = bfc[t];
    if (t < 16) b2s[t] = b2[t];
    __syncthreads();

    int i = blockIdx.x * blockDim.x + threadIdx.x;
    if (i >= n) return;
    float di = g_dinv[i];

    float h2[16];
#pragma unroll
    for (int q = 0; q < 4; q++) {
        float4 tv = g_t2[i * 4 + q];
        float2 s0 = __half22float2(g_hs2h[i * 8 + q * 2 + 0]);
        float2 s1 = __half22float2(g_hs2h[i * 8 + q * 2 + 1]);
        float v;
        v = di * (tv.x + s0.x) + b2s[q * 4 + 0]; h2[q * 4 + 0] = v > 0.f ? v : 0.f;
        v = di * (tv.y + s0.y) + b2s[q * 4 + 1]; h2[q * 4 + 1] = v > 0.f ? v : 0.f;
        v = di * (tv.z + s1.x) + b2s[q * 4 + 2]; h2[q * 4 + 2] = v > 0.f ? v : 0.f;
        v = di * (tv.w + s1.y) + b2s[q * 4 + 3]; h2[q * 4 + 3] = v > 0.f ? v : 0.f;
    }

    float hout[16];
#pragma unroll
    for (int k = 0; k < 16; k++) {
        float ar = bih_s[k], az = bih_s[16 + k], an = bih_s[32 + k];
#pragma unroll
        for (int c = 0; c < 16; c++) {
            float hv = h2[c];
            ar += hv * wih_s[k * 16 + c];
            az += hv * wih_s[(16 + k) * 16 + c];
            an += hv * wih_s[(32 + k) * 16 + c];
        }
        float r = sigmoidf_(ar + bhh_s[k]);
        float z = sigmoidf_(az + bhh_s[16 + k]);
        float nn = tanhf(an + r * bhh_s[32 + k]);
        hout[k] = (1.0f - z) * nn;
    }

    float4* outp = (float4*)(out + (size_t)i * 32);
#pragma unroll
    for (int q = 0; q < 8; q++) {
        float4 o;
        float a0 = bfc_s[q * 4 + 0], a1 = bfc_s[q * 4 + 1];
        float a2 = bfc_s[q * 4 + 2], a3 = bfc_s[q * 4 + 3];
#pragma unroll
        for (int k = 0; k < 16; k++) {
            float hv = hout[k];
            a0 += hv * wfc_s[(q * 4 + 0) * 16 + k];
            a1 += hv * wfc_s[(q * 4 + 1) * 16 + k];
            a2 += hv * wfc_s[(q * 4 + 2) * 16 + k];
            a3 += hv * wfc_s[(q * 4 + 3) * 16 + k];
        }
        o.x = a0; o.y = a1; o.z = a2; o.w = a3;
        outp[q] = o;
    }
}

// ---------------------------------------------------------------------------
extern "C" void kernel_launch(void* const* d_in, const int* in_sizes, int n_in,
                              void* d_out, int out_size) {
    const float* x    = (const float*)d_in[0];
    const int*   ei   = (const int*)  d_in[1];
    const float* W1   = (const float*)d_in[3];
    const float* b1   = (const float*)d_in[4];
    const float* W2   = (const float*)d_in[5];
    const float* b2   = (const float*)d_in[6];
    const float* w_ih = (const float*)d_in[7];
    const float* b_ih = (const float*)d_in[9];
    const float* b_hh = (const float*)d_in[10];
    const float* Wfc  = (const float*)d_in[11];
    const float* bfc  = (const float*)d_in[12];
    float* out = (float*)d_out;

    int n = in_sizes[2];           // N nodes
    int E = in_sizes[1] / 2;       // edges
    const int* src = ei;
    const int* dst = ei + E;

    int nb = (n + 1023) / 1024;    // scan blocks (<=256)

    k_zero_cnt<<<(n + 255) / 256, 256>>>(n);
    k_count<<<(E + 255) / 256, 256>>>(dst, E);
    k_scan1<<<nb, 256>>>(n);
    k_scan2<<<1, 256>>>(nb);
    k_scan3<<<nb, 256>>>(n);
    k_fill<<<(E + 255) / 256, 256>>>(src, dst, E);

    k_gemm1<<<(n + 63) / 64, 256>>>(x, W1, n);

    int n8 = n * 8;
    k_gather<<<(n8 + 255) / 256, 256>>>(n, 0);
    k_combine<<<(n + 255) / 256, 256>>>(W2, b1, n);
    k_gather<<<(n8 + 255) / 256, 256>>>(n, 1);
    k_final<<<(n + 127) / 128, 128>>>(b2, w_ih, b_ih, b_hh, Wfc, bfc, out, n);
}